// round 1
// baseline (speedup 1.0000x reference)
#include <cuda_runtime.h>
#include <cuda_bf16.h>

// Problem constants (fixed shapes for this dataset)
#define NN 100000
#define EE 1600000

// ---------------- scratch (static __device__, no allocation) ----------------
__device__ float g_h[(size_t)NN * 128];    // layer activations (ping buffer)
__device__ float g_st[(size_t)NN * 256];   // fused GEMM output [s | t]
__device__ int   g_deg[NN];
__device__ int   g_rp[NN + 1];             // CSR row_ptr (by dst)
__device__ int   g_cur[NN];                // scatter cursors
__device__ int   g_col[EE];                // CSR col = src sorted by dst
__device__ int   g_bsum[256];
__device__ int   g_boff[256];

// ---------------- CSR build ----------------
__global__ void k_zero_deg(int n) {
    int i = blockIdx.x * blockDim.x + threadIdx.x;
    if (i < n) g_deg[i] = 0;
}

__global__ void k_count(const int* __restrict__ dst, int e) {
    int i = blockIdx.x * blockDim.x + threadIdx.x;
    if (i < e) atomicAdd(&g_deg[dst[i]], 1);
}

// block-level inclusive scan (Hillis-Steele), writes exclusive partials
__global__ void k_scan1(int n) {
    __shared__ int s[512];
    int i = blockIdx.x * 512 + threadIdx.x;
    int v = (i < n) ? g_deg[i] : 0;
    s[threadIdx.x] = v;
    __syncthreads();
    for (int off = 1; off < 512; off <<= 1) {
        int t = (threadIdx.x >= off) ? s[threadIdx.x - off] : 0;
        __syncthreads();
        s[threadIdx.x] += t;
        __syncthreads();
    }
    if (i < n) g_rp[i] = s[threadIdx.x] - v;          // exclusive within block
    if (threadIdx.x == 511) g_bsum[blockIdx.x] = s[511];
}

__global__ void k_scan2(int nb) {
    __shared__ int s[256];
    int v = (threadIdx.x < nb) ? g_bsum[threadIdx.x] : 0;
    s[threadIdx.x] = v;
    __syncthreads();
    for (int off = 1; off < 256; off <<= 1) {
        int t = (threadIdx.x >= off) ? s[threadIdx.x - off] : 0;
        __syncthreads();
        s[threadIdx.x] += t;
        __syncthreads();
    }
    if (threadIdx.x < nb) g_boff[threadIdx.x] = s[threadIdx.x] - v;  // exclusive
}

__global__ void k_scan3(int n, int e) {
    int i = blockIdx.x * 512 + threadIdx.x;
    if (i < n) {
        int r = g_rp[i] + g_boff[blockIdx.x];
        g_rp[i] = r;
        g_cur[i] = r;
    }
    if (i == 0) g_rp[n] = e;
}

__global__ void k_scatter(const int* __restrict__ src, const int* __restrict__ dst, int e) {
    int i = blockIdx.x * blockDim.x + threadIdx.x;
    if (i < e) {
        int d = dst[i];
        int p = atomicAdd(&g_cur[d], 1);
        g_col[p] = src[i];
    }
}

// ---------------- fused GEMM: st[v][0:OUT] = [Ws;Wn] @ in[v] ----------------
// 512 threads, 128 nodes per CTA. Thread = (lane = node-group of 4 strided
// nodes, fg = feature-group of FPT features). in_s rows padded to 129 floats
// (conflict-free strided scalar reads); weights read via warp-broadcast.
// Epilogue: XOR-swizzled smem staging -> coalesced float4 global stores.
template <int OUT>
__global__ __launch_bounds__(512)
void k_gemm(const float* __restrict__ in, const float* __restrict__ ws,
            const float* __restrict__ wn, float* __restrict__ out, int n) {
    extern __shared__ float sm[];
    float* in_s = sm;                 // 128 * 129 floats
    float* w_s  = sm + 128 * 129;     // OUT * 128 floats
    constexpr int HALF = OUT / 2;
    constexpr int FPT  = OUT / 16;
    constexpr int S4   = ((OUT / 4 + 7) & ~7);  // padded float4 row stride for staging

    const int tid  = threadIdx.x;
    const int base = blockIdx.x * 128;

    // load input tile (coalesced), pitch-129 rows
    for (int idx = tid; idx < 128 * 32; idx += 512) {
        int c = idx & 31, nn = idx >> 5;
        float4 v = make_float4(0.f, 0.f, 0.f, 0.f);
        if (base + nn < n)
            v = *(const float4*)(in + (size_t)(base + nn) * 128 + c * 4);
        float* p = in_s + nn * 129 + c * 4;
        p[0] = v.x; p[1] = v.y; p[2] = v.z; p[3] = v.w;
    }
    // load combined weights [Ws; Wn], natural [f][k] layout
    for (int idx = tid; idx < OUT * 32; idx += 512) {
        int c = idx & 31, f = idx >> 5;
        const float* srcw = (f < HALF) ? (ws + (size_t)f * 128)
                                       : (wn + (size_t)(f - HALF) * 128);
        *(float4*)(w_s + f * 128 + c * 4) = *(const float4*)(srcw + c * 4);
    }
    __syncthreads();

    const int lane  = tid & 31;
    const int fg    = tid >> 5;
    const int fbase = fg * FPT;

    float acc[4][FPT];
#pragma unroll
    for (int i = 0; i < 4; i++)
#pragma unroll
        for (int j = 0; j < FPT; j++) acc[i][j] = 0.f;

    const float* ip = in_s + lane * 129;
#pragma unroll 4
    for (int k = 0; k < 128; k++) {
        float a0 = ip[k];
        float a1 = ip[32 * 129 + k];
        float a2 = ip[64 * 129 + k];
        float a3 = ip[96 * 129 + k];
#pragma unroll
        for (int j = 0; j < FPT; j++) {
            float w = w_s[(fbase + j) * 128 + k];   // warp-broadcast
            acc[0][j] = fmaf(a0, w, acc[0][j]);
            acc[1][j] = fmaf(a1, w, acc[1][j]);
            acc[2][j] = fmaf(a2, w, acc[2][j]);
            acc[3][j] = fmaf(a3, w, acc[3][j]);
        }
    }
    __syncthreads();

    // stage to smem with per-row XOR swizzle on float4 granules
    float* o_s = sm;   // reuse (128 * S4 * 4 floats fits)
#pragma unroll
    for (int i = 0; i < 4; i++) {
        int nn = lane + 32 * i;
        int b7 = nn & 7;
#pragma unroll
        for (int j = 0; j < FPT; j++) {
            int f  = fbase + j;
            int pf = (((f >> 2) ^ b7) << 2) | (f & 3);
            o_s[nn * (S4 * 4) + pf] = acc[i][j];
        }
    }
    __syncthreads();

    constexpr int Q = OUT / 4;
    for (int idx = tid; idx < 128 * Q; idx += 512) {
        int c4 = idx % Q, nn = idx / Q;
        if (base + nn < n) {
            float4 v = *(float4*)(o_s + nn * (S4 * 4) + ((c4 ^ (nn & 7)) << 2));
            *(float4*)(out + (size_t)(base + nn) * OUT + c4 * 4) = v;
        }
    }
}

// ---------------- aggregation: out[v] = act(s[v] + mean_t + b) ----------------
__device__ __forceinline__ float4 f4add(float4 a, float4 b) {
    return make_float4(a.x + b.x, a.y + b.y, a.z + b.z, a.w + b.w);
}

// 128-feature layers (SW=256: s at 0, t at 128). One warp per node.
__global__ __launch_bounds__(256)
void k_agg128(const float* __restrict__ st, const float* __restrict__ b,
              float* __restrict__ outh, int n, int relu) {
    int w    = (blockIdx.x * 256 + threadIdx.x) >> 5;
    int lane = threadIdx.x & 31;
    if (w >= n) return;
    int beg = g_rp[w], end = g_rp[w + 1];

    float4 acc = make_float4(0.f, 0.f, 0.f, 0.f);
    for (int e = beg; e < end; e += 4) {
        int i1 = min(e + 1, end - 1);
        int i2 = min(e + 2, end - 1);
        int i3 = min(e + 3, end - 1);
        int u0 = g_col[e], u1 = g_col[i1], u2 = g_col[i2], u3 = g_col[i3];
        float4 v0 = *(const float4*)(st + (size_t)u0 * 256 + 128 + lane * 4);
        float4 v1 = *(const float4*)(st + (size_t)u1 * 256 + 128 + lane * 4);
        float4 v2 = *(const float4*)(st + (size_t)u2 * 256 + 128 + lane * 4);
        float4 v3 = *(const float4*)(st + (size_t)u3 * 256 + 128 + lane * 4);
        acc = f4add(acc, v0);
        if (e + 1 < end) acc = f4add(acc, v1);
        if (e + 2 < end) acc = f4add(acc, v2);
        if (e + 3 < end) acc = f4add(acc, v3);
    }
    float inv = 1.0f / (float)max(end - beg, 1);
    float4 s  = *(const float4*)(st + (size_t)w * 256 + lane * 4);
    float4 bb = *(const float4*)(b + lane * 4);
    float4 r;
    r.x = fmaf(acc.x, inv, s.x + bb.x);
    r.y = fmaf(acc.y, inv, s.y + bb.y);
    r.z = fmaf(acc.z, inv, s.z + bb.z);
    r.w = fmaf(acc.w, inv, s.w + bb.w);
    if (relu) {
        r.x = fmaxf(r.x, 0.f); r.y = fmaxf(r.y, 0.f);
        r.z = fmaxf(r.z, 0.f); r.w = fmaxf(r.w, 0.f);
    }
    *(float4*)(outh + (size_t)w * 128 + lane * 4) = r;
}

// final layer: 40 features (SW=80: s at 0, t at 40). No relu. Writes d_out.
__global__ __launch_bounds__(256)
void k_agg40(const float* __restrict__ st, const float* __restrict__ b,
             float* __restrict__ out, int n) {
    int w    = (blockIdx.x * 256 + threadIdx.x) >> 5;
    int lane = threadIdx.x & 31;
    if (w >= n) return;
    int beg = g_rp[w], end = g_rp[w + 1];

    float a0 = 0.f, a1 = 0.f;
    for (int e = beg; e < end; e += 2) {
        int i1 = min(e + 1, end - 1);
        int u0 = g_col[e], u1 = g_col[i1];
        const float* t0 = st + (size_t)u0 * 80 + 40;
        const float* t1 = st + (size_t)u1 * 80 + 40;
        float p0 = t0[lane];
        float q0 = (lane < 8) ? t0[32 + lane] : 0.f;
        a0 += p0;
        if (lane < 8) a1 += q0;
        if (e + 1 < end) {
            a0 += t1[lane];
            if (lane < 8) a1 += t1[32 + lane];
        }
    }
    float inv = 1.0f / (float)max(end - beg, 1);
    const float* sp = st + (size_t)w * 80;
    if (lane < 40) {  // always true for lane<32, kept for clarity
        out[(size_t)w * 40 + lane] = fmaf(a0, inv, sp[lane] + b[lane]);
    }
    if (lane < 8) {
        int f = 32 + lane;
        out[(size_t)w * 40 + f] = fmaf(a1, inv, sp[f] + b[f]);
    }
}

// ---------------- launch ----------------
extern "C" void kernel_launch(void* const* d_in, const int* in_sizes, int n_in,
                              void* d_out, int out_size) {
    const float* x   = (const float*)d_in[0];
    const int*   src = (const int*)d_in[1];
    const int*   dst = (const int*)d_in[2];
    const float* ws1 = (const float*)d_in[3];
    const float* wn1 = (const float*)d_in[4];
    const float* b1  = (const float*)d_in[5];
    const float* ws2 = (const float*)d_in[6];
    const float* wn2 = (const float*)d_in[7];
    const float* b2  = (const float*)d_in[8];
    const float* ws3 = (const float*)d_in[9];
    const float* wn3 = (const float*)d_in[10];
    const float* b3  = (const float*)d_in[11];
    const float* ws4 = (const float*)d_in[12];
    const float* wn4 = (const float*)d_in[13];
    const float* b4  = (const float*)d_in[14];

    const int n = in_sizes[0] / 128;
    const int E = in_sizes[1];

    const int SMEM256 = (128 * 129 + 256 * 128) * 4;  // 197120 B
    const int SMEM80  = (128 * 129 + 80 * 128) * 4;   // 107008 B
    cudaFuncSetAttribute(k_gemm<256>, cudaFuncAttributeMaxDynamicSharedMemorySize, SMEM256);
    cudaFuncSetAttribute(k_gemm<80>,  cudaFuncAttributeMaxDynamicSharedMemorySize, SMEM80);

    float *ph, *pst;
    cudaGetSymbolAddress((void**)&ph,  g_h);
    cudaGetSymbolAddress((void**)&pst, g_st);

    // CSR build (by dst)
    k_zero_deg<<<(n + 255) / 256, 256>>>(n);
    k_count<<<(E + 255) / 256, 256>>>(dst, E);
    int nb = (n + 511) / 512;
    k_scan1<<<nb, 512>>>(n);
    k_scan2<<<1, 256>>>(nb);
    k_scan3<<<nb, 512>>>(n, E);
    k_scatter<<<(E + 255) / 256, 256>>>(src, dst, E);

    const int gb = (n + 127) / 128;
    const int ga = (n + 7) / 8;

    // L1
    k_gemm<256><<<gb, 512, SMEM256>>>(x, ws1, wn1, pst, n);
    k_agg128<<<ga, 256>>>(pst, b1, ph, n, 1);
    // L2
    k_gemm<256><<<gb, 512, SMEM256>>>(ph, ws2, wn2, pst, n);
    k_agg128<<<ga, 256>>>(pst, b2, ph, n, 1);
    // L3
    k_gemm<256><<<gb, 512, SMEM256>>>(ph, ws3, wn3, pst, n);
    k_agg128<<<ga, 256>>>(pst, b3, ph, n, 1);
    // L4 (40 outputs, no relu) -> d_out
    k_gemm<80><<<gb, 512, SMEM80>>>(ph, ws4, wn4, pst, n);
    k_agg40<<<ga, 256>>>(pst, b4, (float*)d_out, n);
}

// round 3
// speedup vs baseline: 1.9515x; 1.9515x over previous
#include <cuda_runtime.h>
#include <cuda_bf16.h>

#define NN 100000
#define EE 1600000
#define TILES ((NN + 127) / 128)

// ---------------- scratch (static __device__, no allocation) ----------------
// A planes per tile: 4 chunks (h:k0-63, h:k64-127, m:k0-63, m:k64-127),
// each chunk = hi plane + lo plane; plane = 128 rows x 128B (swizzled) = 16KB.
__device__ uint4 g_A[(size_t)TILES * 8 * 1024];   // ~102.5 MB
__device__ uint4 g_B[4 * 8 * 1024];               // per layer: 4 chunks x (hi,lo) 16KB planes
__device__ float g_h[(size_t)NN * 128];
__device__ int   g_deg[NN];
__device__ int   g_rp[NN + 1];
__device__ int   g_cur[NN];
__device__ int   g_col[EE];
__device__ int   g_bsum[256];
__device__ int   g_boff[256];

// ---------------- helpers ----------------
__device__ __forceinline__ int swz(int x) { return x ^ ((x >> 3) & 0x70); }

__device__ __forceinline__ void split4(float4 v, uint2& h, uint2& l) {
    __nv_bfloat16 h0 = __float2bfloat16(v.x), h1 = __float2bfloat16(v.y);
    __nv_bfloat16 h2 = __float2bfloat16(v.z), h3 = __float2bfloat16(v.w);
    __nv_bfloat16 l0 = __float2bfloat16(v.x - __bfloat162float(h0));
    __nv_bfloat16 l1 = __float2bfloat16(v.y - __bfloat162float(h1));
    __nv_bfloat16 l2 = __float2bfloat16(v.z - __bfloat162float(h2));
    __nv_bfloat16 l3 = __float2bfloat16(v.w - __bfloat162float(h3));
    h.x = ((unsigned)__bfloat16_as_ushort(h1) << 16) | __bfloat16_as_ushort(h0);
    h.y = ((unsigned)__bfloat16_as_ushort(h3) << 16) | __bfloat16_as_ushort(h2);
    l.x = ((unsigned)__bfloat16_as_ushort(l1) << 16) | __bfloat16_as_ushort(l0);
    l.y = ((unsigned)__bfloat16_as_ushort(l3) << 16) | __bfloat16_as_ushort(l2);
}

__device__ __forceinline__ unsigned smem_u32(const void* p) {
    unsigned a;
    asm("{ .reg .u64 t; cvta.to.shared.u64 t, %1; cvt.u32.u64 %0, t; }" : "=r"(a) : "l"(p));
    return a;
}
__device__ __forceinline__ void cp16(unsigned s, const void* g) {
    asm volatile("cp.async.cg.shared.global [%0], [%1], 16;" :: "r"(s), "l"(g));
}
__device__ __forceinline__ void cp_commit() { asm volatile("cp.async.commit_group;"); }
__device__ __forceinline__ void cp_wait0() { asm volatile("cp.async.wait_group 0;"); }
__device__ __forceinline__ void cp_wait1() { asm volatile("cp.async.wait_group 1;"); }

__device__ __forceinline__ void ldm_x4(unsigned* r, unsigned addr) {
    asm volatile("ldmatrix.sync.aligned.m8n8.x4.shared.b16 {%0,%1,%2,%3}, [%4];"
                 : "=r"(r[0]), "=r"(r[1]), "=r"(r[2]), "=r"(r[3]) : "r"(addr));
}
__device__ __forceinline__ void mma_bf16(float* d, const unsigned* a, unsigned b0, unsigned b1) {
    asm volatile(
        "mma.sync.aligned.m16n8k16.row.col.f32.bf16.bf16.f32 "
        "{%0,%1,%2,%3}, {%4,%5,%6,%7}, {%8,%9}, {%0,%1,%2,%3};"
        : "+f"(d[0]), "+f"(d[1]), "+f"(d[2]), "+f"(d[3])
        : "r"(a[0]), "r"(a[1]), "r"(a[2]), "r"(a[3]), "r"(b0), "r"(b1));
}

// ---------------- CSR build ----------------
__global__ void k_zero_deg(int n) {
    int i = blockIdx.x * blockDim.x + threadIdx.x;
    if (i < n) g_deg[i] = 0;
}
__global__ void k_count(const int* __restrict__ dst, int e) {
    int i = blockIdx.x * blockDim.x + threadIdx.x;
    if (i < e) atomicAdd(&g_deg[dst[i]], 1);
}
__global__ void k_scan1(int n) {
    __shared__ int s[512];
    int i = blockIdx.x * 512 + threadIdx.x;
    int v = (i < n) ? g_deg[i] : 0;
    s[threadIdx.x] = v;
    __syncthreads();
    for (int off = 1; off < 512; off <<= 1) {
        int t = (threadIdx.x >= off) ? s[threadIdx.x - off] : 0;
        __syncthreads();
        s[threadIdx.x] += t;
        __syncthreads();
    }
    if (i < n) g_rp[i] = s[threadIdx.x] - v;
    if (threadIdx.x == 511) g_bsum[blockIdx.x] = s[511];
}
__global__ void k_scan2(int nb) {
    __shared__ int s[256];
    int v = (threadIdx.x < nb) ? g_bsum[threadIdx.x] : 0;
    s[threadIdx.x] = v;
    __syncthreads();
    for (int off = 1; off < 256; off <<= 1) {
        int t = (threadIdx.x >= off) ? s[threadIdx.x - off] : 0;
        __syncthreads();
        s[threadIdx.x] += t;
        __syncthreads();
    }
    if (threadIdx.x < nb) g_boff[threadIdx.x] = s[threadIdx.x] - v;
}
__global__ void k_scan3(int n, int e) {
    int i = blockIdx.x * 512 + threadIdx.x;
    if (i < n) {
        int r = g_rp[i] + g_boff[blockIdx.x];
        g_rp[i] = r;
        g_cur[i] = r;
    }
    if (i == 0) g_rp[n] = e;
}
__global__ void k_scatter(const int* __restrict__ src, const int* __restrict__ dst, int e) {
    int i = blockIdx.x * blockDim.x + threadIdx.x;
    if (i < e) {
        int d = dst[i];
        int p = atomicAdd(&g_cur[d], 1);
        g_col[p] = src[i];
    }
}

// ---------------- prep: x -> bf16 hi/lo swizzled chunks 0,1 ----------------
__global__ void k_prep_x(const float* __restrict__ x, int n) {
    int idx = blockIdx.x * 256 + threadIdx.x;
    if (idx >= n * 32) return;
    int node = idx >> 5, k = (idx & 31) << 2;
    float4 v = *(const float4*)(x + (size_t)node * 128 + k);
    uint2 h, l;
    split4(v, h, l);
    int tile = node >> 7, r = node & 127, chunk = k >> 6, kb = (k & 63) << 1;
    char* base = (char*)g_A + ((size_t)tile * 4 + chunk) * 2 * 16384;
    int off = ((r >> 3) << 10) + swz(((r & 7) << 7) + kb);
    *(uint2*)(base + off) = h;
    *(uint2*)(base + 16384 + off) = l;
}

// ---------------- prep: weights -> bf16 hi/lo swizzled planes ----------------
__global__ void k_prep_w(const float* __restrict__ ws, const float* __restrict__ wn,
                         int layer, int OUT) {
    int idx = blockIdx.x * 256 + threadIdx.x;  // 128*32
    if (idx >= 4096) return;
    int f = idx >> 5, k = (idx & 31) << 2;
    float4 vs = make_float4(0.f, 0.f, 0.f, 0.f), vn = vs;
    if (f < OUT) {
        vs = *(const float4*)(ws + (size_t)f * 128 + k);
        vn = *(const float4*)(wn + (size_t)f * 128 + k);
    }
    uint2 hs, ls, hn, ln;
    split4(vs, hs, ls);
    split4(vn, hn, ln);
    int chunk = k >> 6, kb = (k & 63) << 1;
    int off = ((f >> 3) << 10) + swz(((f & 7) << 7) + kb);
    char* b0 = (char*)g_B + ((size_t)layer * 4 + chunk) * 2 * 16384;        // ws -> chunks 0,1
    char* b1 = (char*)g_B + ((size_t)layer * 4 + chunk + 2) * 2 * 16384;    // wn -> chunks 2,3
    *(uint2*)(b0 + off) = hs;
    *(uint2*)(b0 + 16384 + off) = ls;
    *(uint2*)(b1 + off) = hn;
    *(uint2*)(b1 + 16384 + off) = ln;
}

// ---------------- aggregation: m[v] = mean_in h[src]; write A chunks 2,3 ----------------
__device__ __forceinline__ float4 f4add(float4 a, float4 b) {
    return make_float4(a.x + b.x, a.y + b.y, a.z + b.z, a.w + b.w);
}
__global__ __launch_bounds__(256)
void k_aggm(const float* __restrict__ h, int n) {
    int w = (blockIdx.x * 256 + threadIdx.x) >> 5;
    int lane = threadIdx.x & 31;
    if (w >= n) return;
    int beg = g_rp[w], end = g_rp[w + 1];

    float4 acc = make_float4(0.f, 0.f, 0.f, 0.f);
    for (int e = beg; e < end; e += 4) {
        int i1 = min(e + 1, end - 1);
        int i2 = min(e + 2, end - 1);
        int i3 = min(e + 3, end - 1);
        int u0 = g_col[e], u1 = g_col[i1], u2 = g_col[i2], u3 = g_col[i3];
        float4 v0 = *(const float4*)(h + (size_t)u0 * 128 + lane * 4);
        float4 v1 = *(const float4*)(h + (size_t)u1 * 128 + lane * 4);
        float4 v2 = *(const float4*)(h + (size_t)u2 * 128 + lane * 4);
        float4 v3 = *(const float4*)(h + (size_t)u3 * 128 + lane * 4);
        acc = f4add(acc, v0);
        if (e + 1 < end) acc = f4add(acc, v1);
        if (e + 2 < end) acc = f4add(acc, v2);
        if (e + 3 < end) acc = f4add(acc, v3);
    }
    float inv = 1.0f / (float)max(end - beg, 1);
    acc.x *= inv; acc.y *= inv; acc.z *= inv; acc.w *= inv;

    uint2 hh, ll;
    split4(acc, hh, ll);
    int tile = w >> 7, r = w & 127;
    int chunk = 2 + (lane >> 4), kb = (lane & 15) << 3;
    char* base = (char*)g_A + ((size_t)tile * 4 + chunk) * 2 * 16384;
    int off = ((r >> 3) << 10) + swz(((r & 7) << 7) + kb);
    *(uint2*)(base + off) = hh;
    *(uint2*)(base + 16384 + off) = ll;
}

// ---------------- mma.sync GEMM: D[128 x NOUT] = A[128 x 256] * B[NOUT x 256]^T ----------------
// 3-term bf16 split; 4 K-chunks of 64; cp.async double-buffered smem; 8 warps in 2(M)x4(N).
template <int NOUT>
__device__ __forceinline__ void prefetch_chunk(char* smembase, int c, const uint4* gAt,
                                               const uint4* __restrict__ Bw, int tid) {
    char* buf = smembase + (c & 1) * 65536;
    const uint4* sa = gAt + (size_t)c * 2048;       // Ah+Al contiguous 32KB
    unsigned da = smem_u32(buf);
#pragma unroll
    for (int i = 0; i < 8; i++) cp16(da + (tid + i * 256) * 16, sa + tid + i * 256);
    const uint4* sb = Bw + (size_t)c * 2048;
    unsigned db = smem_u32(buf + 32768);
    if (NOUT == 128) {
#pragma unroll
        for (int i = 0; i < 8; i++) cp16(db + (tid + i * 256) * 16, sb + tid + i * 256);
    } else {
#pragma unroll
        for (int i = 0; i < 2; i++) cp16(db + (tid + i * 256) * 16, sb + tid + i * 256);
        unsigned dl = smem_u32(buf + 32768 + NOUT * 128);
#pragma unroll
        for (int i = 0; i < 2; i++) cp16(dl + (tid + i * 256) * 16, sb + 1024 + tid + i * 256);
    }
    cp_commit();
}

template <int NOUT>
__global__ __launch_bounds__(256)
void k_gemm_mma(const uint4* __restrict__ Bw, const float* __restrict__ bias,
                float* __restrict__ out, int n) {
    extern __shared__ char smem[];
    constexpr int BPL = NOUT * 128;   // B plane bytes
    constexpr int NPW = NOUT / 4;     // cols per warp
    constexpr int NT  = NPW / 8;      // n8 tiles per warp
    constexpr int NB2 = NPW / 16;     // x4 B-ldmatrix per k-step
    const int tid = threadIdx.x, wid = tid >> 5, lane = tid & 31;
    const int mh = wid >> 2, nq = wid & 3;
    const size_t tile = blockIdx.x;
    const unsigned sbase = smem_u32(smem);

    const uint4* gAt = g_A + tile * 4 * 2048;

    float acc[4][NT][4];
#pragma unroll
    for (int a = 0; a < 4; a++)
#pragma unroll
        for (int b = 0; b < NT; b++)
#pragma unroll
            for (int c = 0; c < 4; c++) acc[a][b][c] = 0.f;

    const int arow = mh * 64 + (lane & 15);                    // + mt*16
    const int brow = nq * NPW + ((lane >> 4) << 3) + (lane & 7);  // + nb*16

    prefetch_chunk<NOUT>(smem, 0, gAt, Bw, tid);

#pragma unroll 1
    for (int c = 0; c < 4; c++) {
        if (c < 3) { prefetch_chunk<NOUT>(smem, c + 1, gAt, Bw, tid); cp_wait1(); }
        else cp_wait0();
        __syncthreads();

        unsigned bufu = sbase + (unsigned)((c & 1) * 65536);
#pragma unroll 1
        for (int t = 0; t < 3; t++) {
            unsigned Ap = bufu + (t == 2 ? 16384u : 0u);
            unsigned Bp = bufu + 32768u + (t == 1 ? (unsigned)BPL : 0u);
#pragma unroll
            for (int ks = 0; ks < 4; ks++) {
                unsigned afr[4][4];
                {
                    int seg = ks * 2 + (lane >> 4);
                    int inner = swz(((arow & 7) << 7) + seg * 16);
#pragma unroll
                    for (int mt = 0; mt < 4; mt++)
                        ldm_x4(afr[mt], Ap + (unsigned)((((arow >> 3) + 2 * mt) << 10) + inner));
                }
                unsigned bfr[NB2][4];
                {
                    int seg = ks * 2 + ((lane >> 3) & 1);
                    int inner = swz(((brow & 7) << 7) + seg * 16);
#pragma unroll
                    for (int nb = 0; nb < NB2; nb++)
                        ldm_x4(bfr[nb], Bp + (unsigned)((((brow >> 3) + 2 * nb) << 10) + inner));
                }
#pragma unroll
                for (int mt = 0; mt < 4; mt++)
#pragma unroll
                    for (int nt = 0; nt < NT; nt++)
                        mma_bf16(acc[mt][nt], afr[mt],
                                 bfr[nt >> 1][(nt & 1) * 2], bfr[nt >> 1][(nt & 1) * 2 + 1]);
            }
        }
        __syncthreads();
    }

    // -------- epilogue: bias(+relu), swizzled smem stage, coalesced writers --------
    constexpr int SSTR = NOUT + 4;
    float* stage = (float*)smem;
    {
        const int rr = lane >> 2, cc = (lane & 3) * 2;
#pragma unroll
        for (int mt = 0; mt < 4; mt++)
#pragma unroll
            for (int nt = 0; nt < NT; nt++) {
                int r = mh * 64 + mt * 16 + rr;
                int col = nq * NPW + nt * 8 + cc;
                float bv0, bv1;
                if (NOUT == 64) {
                    bv0 = (col < 40) ? __ldg(bias + col) : 0.f;
                    bv1 = (col + 1 < 40) ? __ldg(bias + col + 1) : 0.f;
                } else {
                    bv0 = __ldg(bias + col);
                    bv1 = __ldg(bias + col + 1);
                }
                float v0 = acc[mt][nt][0] + bv0, v1 = acc[mt][nt][1] + bv1;
                float v2 = acc[mt][nt][2] + bv0, v3 = acc[mt][nt][3] + bv1;
                if (NOUT == 128) {
                    v0 = fmaxf(v0, 0.f); v1 = fmaxf(v1, 0.f);
                    v2 = fmaxf(v2, 0.f); v3 = fmaxf(v3, 0.f);
                }
                int pg = (((col >> 2) ^ (r & 7)) << 2) + (col & 3);
                stage[r * SSTR + pg] = v0;
                stage[r * SSTR + pg + 1] = v1;
                stage[(r + 8) * SSTR + pg] = v2;
                stage[(r + 8) * SSTR + pg + 1] = v3;
            }
    }
    __syncthreads();

    constexpr int Q = NOUT / 4;
    const size_t base = tile * 128;
    for (int t = tid; t < 128 * Q; t += 256) {
        int nn = t / Q, c4 = t % Q;
        size_t gn = base + nn;
        if (gn < (size_t)n) {
            float4 o = *(float4*)(stage + nn * SSTR + ((c4 ^ (nn & 7)) << 2));
            if (NOUT == 128) {
                *(float4*)(out + gn * 128 + c4 * 4) = o;
                uint2 hh, ll;
                split4(o, hh, ll);
                int k0 = c4 * 4;
                int chunk = k0 >> 6, kb = (k0 & 63) << 1;
                char* bA = (char*)g_A + (tile * 4 + chunk) * 2 * 16384;
                int off = ((nn >> 3) << 10) + swz(((nn & 7) << 7) + kb);
                *(uint2*)(bA + off) = hh;
                *(uint2*)(bA + 16384 + off) = ll;
            } else {
                int col = c4 * 4;
                if (col < 40) *(float4*)(out + gn * 40 + col) = o;
            }
        }
    }
}

// ---------------- launch ----------------
extern "C" void kernel_launch(void* const* d_in, const int* in_sizes, int n_in,
                              void* d_out, int out_size) {
    const float* x   = (const float*)d_in[0];
    const int*   src = (const int*)d_in[1];
    const int*   dst = (const int*)d_in[2];
    const float* ws1 = (const float*)d_in[3];
    const float* wn1 = (const float*)d_in[4];
    const float* b1  = (const float*)d_in[5];
    const float* ws2 = (const float*)d_in[6];
    const float* wn2 = (const float*)d_in[7];
    const float* b2  = (const float*)d_in[8];
    const float* ws3 = (const float*)d_in[9];
    const float* wn3 = (const float*)d_in[10];
    const float* b3  = (const float*)d_in[11];
    const float* ws4 = (const float*)d_in[12];
    const float* wn4 = (const float*)d_in[13];
    const float* b4  = (const float*)d_in[14];

    const int n = in_sizes[0] / 128;
    const int E = in_sizes[1];
    const int tiles = (n + 127) / 128;

    const int SMEM = 2 * 65536;  // 131072
    cudaFuncSetAttribute(k_gemm_mma<128>, cudaFuncAttributeMaxDynamicSharedMemorySize, SMEM);
    cudaFuncSetAttribute(k_gemm_mma<64>,  cudaFuncAttributeMaxDynamicSharedMemorySize, SMEM);

    float* ph;
    uint4* pB;
    cudaGetSymbolAddress((void**)&ph, g_h);
    cudaGetSymbolAddress((void**)&pB, g_B);

    // CSR build (by dst)
    k_zero_deg<<<(n + 255) / 256, 256>>>(n);
    k_count<<<(E + 255) / 256, 256>>>(dst, E);
    int nb = (n + 511) / 512;
    k_scan1<<<nb, 512>>>(n);
    k_scan2<<<1, 256>>>(nb);
    k_scan3<<<nb, 512>>>(n, E);
    k_scatter<<<(E + 255) / 256, 256>>>(src, dst, E);

    // preps
    k_prep_x<<<(n * 32 + 255) / 256, 256>>>(x, n);
    k_prep_w<<<16, 256>>>(ws1, wn1, 0, 128);
    k_prep_w<<<16, 256>>>(ws2, wn2, 1, 128);
    k_prep_w<<<16, 256>>>(ws3, wn3, 2, 128);
    k_prep_w<<<16, 256>>>(ws4, wn4, 3, 40);

    const int ga = (n + 7) / 8;

    // L1
    k_aggm<<<ga, 256>>>(x, n);
    k_gemm_mma<128><<<tiles, 256, SMEM>>>(pB + 0 * 8192, b1, ph, n);
    // L2
    k_aggm<<<ga, 256>>>(ph, n);
    k_gemm_mma<128><<<tiles, 256, SMEM>>>(pB + 1 * 8192, b2, ph, n);
    // L3
    k_aggm<<<ga, 256>>>(ph, n);
    k_gemm_mma<128><<<tiles, 256, SMEM>>>(pB + 2 * 8192, b3, ph, n);
    // L4 -> d_out (40 cols)
    k_aggm<<<ga, 256>>>(ph, n);
    k_gemm_mma<64><<<tiles, 256, SMEM>>>(pB + 3 * 8192, b4, (float*)d_out, n);
}

// round 4
// speedup vs baseline: 2.0848x; 1.0683x over previous
#include <cuda_runtime.h>
#include <cuda_bf16.h>
#include <cuda_fp16.h>

#define NN 100000
#define EE 1600000
#define TILES ((NN + 127) / 128)

// ---------------- scratch (static __device__, no allocation) ----------------
// A planes per tile: 4 chunks (h:k0-63, h:k64-127, m:k0-63, m:k64-127),
// each chunk = hi plane + lo plane; plane = 128 rows x 128B (swizzled) = 16KB.
__device__ uint4 g_A[(size_t)TILES * 8 * 1024];   // ~102.5 MB
__device__ uint4 g_B[4 * 8 * 1024];               // per layer: 4 chunks x (hi,lo) 16KB planes
__device__ uint2 g_hh[(size_t)NN * 32];           // h (or x) in fp16, 128 feats = 32 uint2
__device__ float g_st[(size_t)NN * 80];           // layer-4 GEMM out: s(40) | t(40)
__device__ int   g_deg[NN];
__device__ int   g_rp[NN + 1];
__device__ int   g_cur[NN];
__device__ int   g_col[EE];
__device__ int   g_bsum[256];
__device__ int   g_boff[256];

// ---------------- helpers ----------------
__device__ __forceinline__ int swz(int x) { return x ^ ((x >> 3) & 0x70); }

__device__ __forceinline__ void split4(float4 v, uint2& h, uint2& l) {
    __nv_bfloat16 h0 = __float2bfloat16(v.x), h1 = __float2bfloat16(v.y);
    __nv_bfloat16 h2 = __float2bfloat16(v.z), h3 = __float2bfloat16(v.w);
    __nv_bfloat16 l0 = __float2bfloat16(v.x - __bfloat162float(h0));
    __nv_bfloat16 l1 = __float2bfloat16(v.y - __bfloat162float(h1));
    __nv_bfloat16 l2 = __float2bfloat16(v.z - __bfloat162float(h2));
    __nv_bfloat16 l3 = __float2bfloat16(v.w - __bfloat162float(h3));
    h.x = ((unsigned)__bfloat16_as_ushort(h1) << 16) | __bfloat16_as_ushort(h0);
    h.y = ((unsigned)__bfloat16_as_ushort(h3) << 16) | __bfloat16_as_ushort(h2);
    l.x = ((unsigned)__bfloat16_as_ushort(l1) << 16) | __bfloat16_as_ushort(l0);
    l.y = ((unsigned)__bfloat16_as_ushort(l3) << 16) | __bfloat16_as_ushort(l2);
}

__device__ __forceinline__ uint2 pack_h4(float4 v) {
    __half2 a = __float22half2_rn(make_float2(v.x, v.y));
    __half2 b = __float22half2_rn(make_float2(v.z, v.w));
    uint2 r;
    r.x = *(unsigned*)&a;
    r.y = *(unsigned*)&b;
    return r;
}

__device__ __forceinline__ unsigned smem_u32(const void* p) {
    unsigned a;
    asm("{ .reg .u64 t; cvta.to.shared.u64 t, %1; cvt.u32.u64 %0, t; }" : "=r"(a) : "l"(p));
    return a;
}
__device__ __forceinline__ void cp16(unsigned s, const void* g) {
    asm volatile("cp.async.cg.shared.global [%0], [%1], 16;" :: "r"(s), "l"(g));
}
__device__ __forceinline__ void cp_commit() { asm volatile("cp.async.commit_group;"); }
__device__ __forceinline__ void cp_wait0() { asm volatile("cp.async.wait_group 0;"); }
__device__ __forceinline__ void cp_wait1() { asm volatile("cp.async.wait_group 1;"); }

__device__ __forceinline__ void ldm_x4(unsigned* r, unsigned addr) {
    asm volatile("ldmatrix.sync.aligned.m8n8.x4.shared.b16 {%0,%1,%2,%3}, [%4];"
                 : "=r"(r[0]), "=r"(r[1]), "=r"(r[2]), "=r"(r[3]) : "r"(addr));
}
__device__ __forceinline__ void mma_bf16(float* d, const unsigned* a, unsigned b0, unsigned b1) {
    asm volatile(
        "mma.sync.aligned.m16n8k16.row.col.f32.bf16.bf16.f32 "
        "{%0,%1,%2,%3}, {%4,%5,%6,%7}, {%8,%9}, {%0,%1,%2,%3};"
        : "+f"(d[0]), "+f"(d[1]), "+f"(d[2]), "+f"(d[3])
        : "r"(a[0]), "r"(a[1]), "r"(a[2]), "r"(a[3]), "r"(b0), "r"(b1));
}

// ---------------- CSR build ----------------
__global__ void k_zero_deg(int n) {
    int i = blockIdx.x * blockDim.x + threadIdx.x;
    if (i < n) g_deg[i] = 0;
}
__global__ void k_count(const int* __restrict__ dst, int e) {
    int i = blockIdx.x * blockDim.x + threadIdx.x;
    if (i < e) atomicAdd(&g_deg[dst[i]], 1);
}
__global__ void k_scan1(int n) {
    __shared__ int s[512];
    int i = blockIdx.x * 512 + threadIdx.x;
    int v = (i < n) ? g_deg[i] : 0;
    s[threadIdx.x] = v;
    __syncthreads();
    for (int off = 1; off < 512; off <<= 1) {
        int t = (threadIdx.x >= off) ? s[threadIdx.x - off] : 0;
        __syncthreads();
        s[threadIdx.x] += t;
        __syncthreads();
    }
    if (i < n) g_rp[i] = s[threadIdx.x] - v;
    if (threadIdx.x == 511) g_bsum[blockIdx.x] = s[511];
}
__global__ void k_scan2(int nb) {
    __shared__ int s[256];
    int v = (threadIdx.x < nb) ? g_bsum[threadIdx.x] : 0;
    s[threadIdx.x] = v;
    __syncthreads();
    for (int off = 1; off < 256; off <<= 1) {
        int t = (threadIdx.x >= off) ? s[threadIdx.x - off] : 0;
        __syncthreads();
        s[threadIdx.x] += t;
        __syncthreads();
    }
    if (threadIdx.x < nb) g_boff[threadIdx.x] = s[threadIdx.x] - v;
}
__global__ void k_scan3(int n, int e) {
    int i = blockIdx.x * 512 + threadIdx.x;
    if (i < n) {
        int r = g_rp[i] + g_boff[blockIdx.x];
        g_rp[i] = r;
        g_cur[i] = r;
    }
    if (i == 0) g_rp[n] = e;
}
__global__ void k_scatter(const int* __restrict__ src, const int* __restrict__ dst, int e) {
    int i = blockIdx.x * blockDim.x + threadIdx.x;
    if (i < e) {
        int d = dst[i];
        int p = atomicAdd(&g_cur[d], 1);
        g_col[p] = src[i];
    }
}

// ---------------- prep: x -> bf16 hi/lo swizzled chunks 0,1 + fp16 copy ----------------
__global__ void k_prep_x(const float* __restrict__ x, int n) {
    int idx = blockIdx.x * 256 + threadIdx.x;
    if (idx >= n * 32) return;
    int node = idx >> 5, k = (idx & 31) << 2;
    float4 v = *(const float4*)(x + (size_t)node * 128 + k);
    uint2 h, l;
    split4(v, h, l);
    int tile = node >> 7, r = node & 127, chunk = k >> 6, kb = (k & 63) << 1;
    char* base = (char*)g_A + ((size_t)tile * 4 + chunk) * 2 * 16384;
    int off = ((r >> 3) << 10) + swz(((r & 7) << 7) + kb);
    *(uint2*)(base + off) = h;
    *(uint2*)(base + 16384 + off) = l;
    g_hh[(size_t)node * 32 + (k >> 2)] = pack_h4(v);
}

// ---------------- prep: weights (layers 1-3) -> bf16 hi/lo swizzled planes ----------------
__global__ void k_prep_w(const float* __restrict__ ws, const float* __restrict__ wn,
                         int layer, int OUT) {
    int idx = blockIdx.x * 256 + threadIdx.x;  // 128*32
    if (idx >= 4096) return;
    int f = idx >> 5, k = (idx & 31) << 2;
    float4 vs = make_float4(0.f, 0.f, 0.f, 0.f), vn = vs;
    if (f < OUT) {
        vs = *(const float4*)(ws + (size_t)f * 128 + k);
        vn = *(const float4*)(wn + (size_t)f * 128 + k);
    }
    uint2 hs, ls, hn, ln;
    split4(vs, hs, ls);
    split4(vn, hn, ln);
    int chunk = k >> 6, kb = (k & 63) << 1;
    int off = ((f >> 3) << 10) + swz(((f & 7) << 7) + kb);
    char* b0 = (char*)g_B + ((size_t)layer * 4 + chunk) * 2 * 16384;        // ws -> chunks 0,1
    char* b1 = (char*)g_B + ((size_t)layer * 4 + chunk + 2) * 2 * 16384;    // wn -> chunks 2,3
    *(uint2*)(b0 + off) = hs;
    *(uint2*)(b0 + 16384 + off) = ls;
    *(uint2*)(b1 + off) = hn;
    *(uint2*)(b1 + 16384 + off) = ln;
}

// ---------------- prep: layer 4 weights, stacked [Ws4(40); Wn4(40); 0] over K=128 ----------------
__global__ void k_prep_w4(const float* __restrict__ ws, const float* __restrict__ wn) {
    int idx = blockIdx.x * 256 + threadIdx.x;  // 128 rows * 32 granules
    if (idx >= 4096) return;
    int f = idx >> 5, k = (idx & 31) << 2;
    float4 v = make_float4(0.f, 0.f, 0.f, 0.f);
    if (f < 40) v = *(const float4*)(ws + (size_t)f * 128 + k);
    else if (f < 80) v = *(const float4*)(wn + (size_t)(f - 40) * 128 + k);
    uint2 h, l;
    split4(v, h, l);
    int chunk = k >> 6, kb = (k & 63) << 1;
    int off = ((f >> 3) << 10) + swz(((f & 7) << 7) + kb);
    char* b0 = (char*)g_B + ((size_t)3 * 4 + chunk) * 2 * 16384;
    *(uint2*)(b0 + off) = h;
    *(uint2*)(b0 + 16384 + off) = l;
}

// ---------------- aggregation: m[v] = mean_in h_fp16[src]; write A chunks 2,3 ----------------
__global__ __launch_bounds__(256)
void k_aggm(int n) {
    int w = (blockIdx.x * 256 + threadIdx.x) >> 5;
    int lane = threadIdx.x & 31;
    if (w >= n) return;
    int beg = g_rp[w], end = g_rp[w + 1];

    float4 acc = make_float4(0.f, 0.f, 0.f, 0.f);
    for (int e = beg; e < end; e += 4) {
        int i1 = min(e + 1, end - 1);
        int i2 = min(e + 2, end - 1);
        int i3 = min(e + 3, end - 1);
        int u0 = g_col[e], u1 = g_col[i1], u2 = g_col[i2], u3 = g_col[i3];
        uint2 q0 = g_hh[(size_t)u0 * 32 + lane];
        uint2 q1 = g_hh[(size_t)u1 * 32 + lane];
        uint2 q2 = g_hh[(size_t)u2 * 32 + lane];
        uint2 q3 = g_hh[(size_t)u3 * 32 + lane];
#define ACC4(q) do { \
        float2 f0 = __half22float2(*(__half2*)&(q).x); \
        float2 f1 = __half22float2(*(__half2*)&(q).y); \
        acc.x += f0.x; acc.y += f0.y; acc.z += f1.x; acc.w += f1.y; } while (0)
        ACC4(q0);
        if (e + 1 < end) ACC4(q1);
        if (e + 2 < end) ACC4(q2);
        if (e + 3 < end) ACC4(q3);
#undef ACC4
    }
    float inv = 1.0f / (float)max(end - beg, 1);
    acc.x *= inv; acc.y *= inv; acc.z *= inv; acc.w *= inv;

    uint2 hh, ll;
    split4(acc, hh, ll);
    int tile = w >> 7, r = w & 127;
    int chunk = 2 + (lane >> 4), kb = (lane & 15) << 3;
    char* base = (char*)g_A + ((size_t)tile * 4 + chunk) * 2 * 16384;
    int off = ((r >> 3) << 10) + swz(((r & 7) << 7) + kb);
    *(uint2*)(base + off) = hh;
    *(uint2*)(base + 16384 + off) = ll;
}

// ---------------- mma.sync GEMM: D[128 x 128] = A[128 x 64*NC] * B[128 x 64*NC]^T ----------------
// 3-term bf16 split; NC K-chunks of 64; cp.async double-buffered smem; 8 warps 2(M)x4(N).
__device__ __forceinline__ void prefetch_chunk(char* smembase, int c, const uint4* gAt,
                                               const uint4* __restrict__ Bw, int tid) {
    char* buf = smembase + (c & 1) * 65536;
    const uint4* sa = gAt + (size_t)c * 2048;       // Ah+Al contiguous 32KB
    unsigned da = smem_u32(buf);
#pragma unroll
    for (int i = 0; i < 8; i++) cp16(da + (tid + i * 256) * 16, sa + tid + i * 256);
    const uint4* sb = Bw + (size_t)c * 2048;        // Bh+Bl contiguous 32KB
    unsigned db = smem_u32(buf + 32768);
#pragma unroll
    for (int i = 0; i < 8; i++) cp16(db + (tid + i * 256) * 16, sb + tid + i * 256);
    cp_commit();
}

template <int NC, bool FINAL>
__global__ __launch_bounds__(256)
void k_gemm_mma(const uint4* __restrict__ Bw, const float* __restrict__ bias,
                float* __restrict__ out, int n) {
    extern __shared__ char smem[];
    const int tid = threadIdx.x, wid = tid >> 5, lane = tid & 31;
    const int mh = wid >> 2, nq = wid & 3;
    const size_t tile = blockIdx.x;
    const unsigned sbase = smem_u32(smem);

    const uint4* gAt = g_A + tile * 4 * 2048;

    float acc[4][4][4];
#pragma unroll
    for (int a = 0; a < 4; a++)
#pragma unroll
        for (int b = 0; b < 4; b++)
#pragma unroll
            for (int c = 0; c < 4; c++) acc[a][b][c] = 0.f;

    const int arow = mh * 64 + (lane & 15);
    const int brow = nq * 32 + ((lane >> 4) << 3) + (lane & 7);

    prefetch_chunk(smem, 0, gAt, Bw, tid);

#pragma unroll 1
    for (int c = 0; c < NC; c++) {
        if (c < NC - 1) { prefetch_chunk(smem, c + 1, gAt, Bw, tid); cp_wait1(); }
        else cp_wait0();
        __syncthreads();

        unsigned bufu = sbase + (unsigned)((c & 1) * 65536);
#pragma unroll 1
        for (int t = 0; t < 3; t++) {
            unsigned Ap = bufu + (t == 2 ? 16384u : 0u);
            unsigned Bp = bufu + 32768u + (t == 1 ? 16384u : 0u);
#pragma unroll
            for (int ks = 0; ks < 4; ks++) {
                unsigned afr[4][4];
                {
                    int seg = ks * 2 + (lane >> 4);
                    int inner = swz(((arow & 7) << 7) + seg * 16);
#pragma unroll
                    for (int mt = 0; mt < 4; mt++)
                        ldm_x4(afr[mt], Ap + (unsigned)((((arow >> 3) + 2 * mt) << 10) + inner));
                }
                unsigned bfr[2][4];
                {
                    int seg = ks * 2 + ((lane >> 3) & 1);
                    int inner = swz(((brow & 7) << 7) + seg * 16);
#pragma unroll
                    for (int nb = 0; nb < 2; nb++)
                        ldm_x4(bfr[nb], Bp + (unsigned)((((brow >> 3) + 2 * nb) << 10) + inner));
                }
#pragma unroll
                for (int mt = 0; mt < 4; mt++)
#pragma unroll
                    for (int nt = 0; nt < 4; nt++)
                        mma_bf16(acc[mt][nt], afr[mt],
                                 bfr[nt >> 1][(nt & 1) * 2], bfr[nt >> 1][(nt & 1) * 2 + 1]);
            }
        }
        __syncthreads();
    }

    // -------- epilogue --------
    constexpr int SSTR = 132;
    float* stage = (float*)smem;
    {
        const int rr = lane >> 2, cc = (lane & 3) * 2;
#pragma unroll
        for (int mt = 0; mt < 4; mt++)
#pragma unroll
            for (int nt = 0; nt < 4; nt++) {
                int r = mh * 64 + mt * 16 + rr;
                int col = nq * 32 + nt * 8 + cc;
                float bv0 = 0.f, bv1 = 0.f;
                if (!FINAL) {
                    bv0 = __ldg(bias + col);
                    bv1 = __ldg(bias + col + 1);
                }
                float v0 = acc[mt][nt][0] + bv0, v1 = acc[mt][nt][1] + bv1;
                float v2 = acc[mt][nt][2] + bv0, v3 = acc[mt][nt][3] + bv1;
                if (!FINAL) {
                    v0 = fmaxf(v0, 0.f); v1 = fmaxf(v1, 0.f);
                    v2 = fmaxf(v2, 0.f); v3 = fmaxf(v3, 0.f);
                }
                int pg = (((col >> 2) ^ (r & 7)) << 2) + (col & 3);
                stage[r * SSTR + pg] = v0;
                stage[r * SSTR + pg + 1] = v1;
                stage[(r + 8) * SSTR + pg] = v2;
                stage[(r + 8) * SSTR + pg + 1] = v3;
            }
    }
    __syncthreads();

    const size_t base = tile * 128;
    for (int t = tid; t < 128 * 32; t += 256) {
        int nn = t >> 5, c4 = t & 31;
        size_t gn = base + nn;
        if (gn < (size_t)n) {
            float4 o = *(float4*)(stage + nn * SSTR + ((c4 ^ (nn & 7)) << 2));
            if (FINAL) {
                int col = c4 * 4;
                if (col < 80) *(float4*)(out + gn * 80 + col) = o;
            } else {
                // next layer: fp16 copy for aggregation
                g_hh[gn * 32 + c4] = pack_h4(o);
                // next layer: A chunks 0,1 bf16 hi/lo swizzled
                uint2 hh, ll;
                split4(o, hh, ll);
                int k0 = c4 * 4;
                int chunk = k0 >> 6, kb = (k0 & 63) << 1;
                char* bA = (char*)g_A + (tile * 4 + chunk) * 2 * 16384;
                int off = ((nn >> 3) << 10) + swz(((nn & 7) << 7) + kb);
                *(uint2*)(bA + off) = hh;
                *(uint2*)(bA + 16384 + off) = ll;
            }
        }
    }
}

// ---------------- final aggregation: out[v] = s[v] + mean_t + b ----------------
__global__ __launch_bounds__(256)
void k_aggf(const float* __restrict__ st, const float* __restrict__ b,
            float* __restrict__ out, int n) {
    int w = (blockIdx.x * 256 + threadIdx.x) >> 5;
    int lane = threadIdx.x & 31;
    if (w >= n) return;
    int beg = g_rp[w], end = g_rp[w + 1];

    float a0 = 0.f, a1 = 0.f;
    for (int e = beg; e < end; e += 2) {
        int i1 = min(e + 1, end - 1);
        int u0 = g_col[e], u1 = g_col[i1];
        const float* t0 = st + (size_t)u0 * 80 + 40;
        const float* t1 = st + (size_t)u1 * 80 + 40;
        a0 += t0[lane];
        if (lane < 8) a1 += t0[32 + lane];
        if (e + 1 < end) {
            a0 += t1[lane];
            if (lane < 8) a1 += t1[32 + lane];
        }
    }
    float inv = 1.0f / (float)max(end - beg, 1);
    const float* sp = st + (size_t)w * 80;
    out[(size_t)w * 40 + lane] = fmaf(a0, inv, sp[lane] + __ldg(b + lane));
    if (lane < 8) {
        int f = 32 + lane;
        out[(size_t)w * 40 + f] = fmaf(a1, inv, sp[f] + __ldg(b + f));
    }
}

// ---------------- launch ----------------
extern "C" void kernel_launch(void* const* d_in, const int* in_sizes, int n_in,
                              void* d_out, int out_size) {
    const float* x   = (const float*)d_in[0];
    const int*   src = (const int*)d_in[1];
    const int*   dst = (const int*)d_in[2];
    const float* ws1 = (const float*)d_in[3];
    const float* wn1 = (const float*)d_in[4];
    const float* b1  = (const float*)d_in[5];
    const float* ws2 = (const float*)d_in[6];
    const float* wn2 = (const float*)d_in[7];
    const float* b2  = (const float*)d_in[8];
    const float* ws3 = (const float*)d_in[9];
    const float* wn3 = (const float*)d_in[10];
    const float* b3  = (const float*)d_in[11];
    const float* ws4 = (const float*)d_in[12];
    const float* wn4 = (const float*)d_in[13];
    const float* b4  = (const float*)d_in[14];

    const int n = in_sizes[0] / 128;
    const int E = in_sizes[1];
    const int tiles = (n + 127) / 128;

    const int SMEM = 2 * 65536;
    cudaFuncSetAttribute(k_gemm_mma<4, false>, cudaFuncAttributeMaxDynamicSharedMemorySize, SMEM);
    cudaFuncSetAttribute(k_gemm_mma<2, true>,  cudaFuncAttributeMaxDynamicSharedMemorySize, SMEM);

    float* pst;
    uint4* pB;
    cudaGetSymbolAddress((void**)&pst, g_st);
    cudaGetSymbolAddress((void**)&pB, g_B);

    // CSR build (by dst)
    k_zero_deg<<<(n + 255) / 256, 256>>>(n);
    k_count<<<(E + 255) / 256, 256>>>(dst, E);
    int nb = (n + 511) / 512;
    k_scan1<<<nb, 512>>>(n);
    k_scan2<<<1, 256>>>(nb);
    k_scan3<<<nb, 512>>>(n, E);
    k_scatter<<<(E + 255) / 256, 256>>>(src, dst, E);

    // preps
    k_prep_x<<<(n * 32 + 255) / 256, 256>>>(x, n);
    k_prep_w<<<16, 256>>>(ws1, wn1, 0, 128);
    k_prep_w<<<16, 256>>>(ws2, wn2, 1, 128);
    k_prep_w<<<16, 256>>>(ws3, wn3, 2, 128);
    k_prep_w4<<<16, 256>>>(ws4, wn4);

    const int ga = (n + 7) / 8;

    // L1..L3: aggregate-then-GEMM (fused [Ws|Wn], relu)
    k_aggm<<<ga, 256>>>(n);
    k_gemm_mma<4, false><<<tiles, 256, SMEM>>>(pB + 0 * 8192, b1, nullptr, n);
    k_aggm<<<ga, 256>>>(n);
    k_gemm_mma<4, false><<<tiles, 256, SMEM>>>(pB + 1 * 8192, b2, nullptr, n);
    k_aggm<<<ga, 256>>>(n);
    k_gemm_mma<4, false><<<tiles, 256, SMEM>>>(pB + 2 * 8192, b3, nullptr, n);
    // L4: GEMM-then-gather (st = [Ws4;Wn4] h3, K=128), then final agg -> d_out
    k_gemm_mma<2, true><<<tiles, 256, SMEM>>>(pB + 3 * 8192, b4, pst, n);
    k_aggf<<<ga, 256>>>(pst, b4, (float*)d_out, n);
}

// round 5
// speedup vs baseline: 3.0303x; 1.4536x over previous
#include <cuda_runtime.h>
#include <cuda_fp16.h>

#define NN 100000
#define EE 1600000
#define TILES ((NN + 127) / 128)

// ---------------- scratch (static __device__, no allocation) ----------------
// Per tile: 4 fp16 planes (h:k0-63, h:k64-127, m:k0-63, m:k64-127).
// Plane = 128 rows x 128B (64 fp16, SW128-swizzled within row) = 16KB.
__device__ uint4 g_A[(size_t)TILES * 4 * 1024];   // ~51 MB
__device__ uint4 g_B[4 * 4 * 1024];               // per layer: 4 chunk planes, fp16
__device__ float g_st[(size_t)NN * 80];           // layer-4 GEMM out: s(40) | t(40)
__device__ int   g_deg[NN];
__device__ int   g_rp[NN + 1];
__device__ int   g_cur[NN];
__device__ int   g_col[EE];
__device__ int   g_bsum[256];

// ---------------- helpers ----------------
__device__ __forceinline__ int swz(int x) { return x ^ ((x >> 3) & 0x70); }

__device__ __forceinline__ uint2 pack_h4(float4 v) {
    __half2 a = __floats2half2_rn(v.x, v.y);
    __half2 b = __floats2half2_rn(v.z, v.w);
    uint2 r;
    r.x = *(unsigned*)&a;
    r.y = *(unsigned*)&b;
    return r;
}

__device__ __forceinline__ unsigned smem_u32(const void* p) {
    unsigned a;
    asm("{ .reg .u64 t; cvta.to.shared.u64 t, %1; cvt.u32.u64 %0, t; }" : "=r"(a) : "l"(p));
    return a;
}
__device__ __forceinline__ void cp16(unsigned s, const void* g) {
    asm volatile("cp.async.cg.shared.global [%0], [%1], 16;" :: "r"(s), "l"(g));
}
__device__ __forceinline__ void cp_commit() { asm volatile("cp.async.commit_group;"); }
__device__ __forceinline__ void cp_wait0() { asm volatile("cp.async.wait_group 0;"); }
__device__ __forceinline__ void cp_wait1() { asm volatile("cp.async.wait_group 1;"); }

__device__ __forceinline__ void ldm_x4(unsigned* r, unsigned addr) {
    asm volatile("ldmatrix.sync.aligned.m8n8.x4.shared.b16 {%0,%1,%2,%3}, [%4];"
                 : "=r"(r[0]), "=r"(r[1]), "=r"(r[2]), "=r"(r[3]) : "r"(addr));
}
__device__ __forceinline__ void mma_f16(float* d, const unsigned* a, unsigned b0, unsigned b1) {
    asm volatile(
        "mma.sync.aligned.m16n8k16.row.col.f32.f16.f16.f32 "
        "{%0,%1,%2,%3}, {%4,%5,%6,%7}, {%8,%9}, {%0,%1,%2,%3};"
        : "+f"(d[0]), "+f"(d[1]), "+f"(d[2]), "+f"(d[3])
        : "r"(a[0]), "r"(a[1]), "r"(a[2]), "r"(a[3]), "r"(b0), "r"(b1));
}

// ---------------- prep: x -> fp16 planes (chunks 0,1); also zero deg ----------------
__global__ void k_prep_x(const float* __restrict__ x, int n) {
    int idx = blockIdx.x * 256 + threadIdx.x;
    if (idx < n) g_deg[idx] = 0;
    if (idx >= n * 32) return;
    int node = idx >> 5, k = (idx & 31) << 2;
    float4 v = *(const float4*)(x + (size_t)node * 128 + k);
    uint2 q = pack_h4(v);
    int tile = node >> 7, r = node & 127, chunk = k >> 6, kb = (k & 63) << 1;
    char* base = (char*)g_A + ((size_t)tile * 4 + chunk) * 16384;
    int off = ((r >> 3) << 10) + swz(((r & 7) << 7) + kb);
    *(uint2*)(base + off) = q;
}

// ---------------- prep: all weights -> fp16 planes ----------------
__global__ void k_prep_wall(const float* __restrict__ ws1, const float* __restrict__ wn1,
                            const float* __restrict__ ws2, const float* __restrict__ wn2,
                            const float* __restrict__ ws3, const float* __restrict__ wn3,
                            const float* __restrict__ ws4, const float* __restrict__ wn4) {
    int layer = blockIdx.y;
    int idx = blockIdx.x * 256 + threadIdx.x;   // 0..4095
    if (idx >= 4096) return;
    int f = idx >> 5, k = (idx & 31) << 2;
    int kb = (k & 63) << 1;
    int off = ((f >> 3) << 10) + swz(((f & 7) << 7) + kb);
    if (layer < 3) {
        const float* ws = (layer == 0) ? ws1 : (layer == 1) ? ws2 : ws3;
        const float* wn = (layer == 0) ? wn1 : (layer == 1) ? wn2 : wn3;
        float4 vs = *(const float4*)(ws + (size_t)f * 128 + k);
        float4 vn = *(const float4*)(wn + (size_t)f * 128 + k);
        int chunk = k >> 6;
        char* b0 = (char*)g_B + ((size_t)layer * 4 + chunk) * 16384;
        char* b1 = (char*)g_B + ((size_t)layer * 4 + chunk + 2) * 16384;
        *(uint2*)(b0 + off) = pack_h4(vs);
        *(uint2*)(b1 + off) = pack_h4(vn);
    } else {
        // layer 4: stacked [Ws4(40); Wn4(40); 0], K=128 -> chunks 0,1
        float4 v = make_float4(0.f, 0.f, 0.f, 0.f);
        if (f < 40) v = *(const float4*)(ws4 + (size_t)f * 128 + k);
        else if (f < 80) v = *(const float4*)(wn4 + (size_t)(f - 40) * 128 + k);
        int chunk = k >> 6;
        char* b0 = (char*)g_B + ((size_t)3 * 4 + chunk) * 16384;
        *(uint2*)(b0 + off) = pack_h4(v);
    }
}

// ---------------- CSR build ----------------
__global__ void k_count(const int* __restrict__ dst, int e) {
    int i = blockIdx.x * blockDim.x + threadIdx.x;
    if (i < e) atomicAdd(&g_deg[dst[i]], 1);
}
__global__ void k_scan1(int n) {
    __shared__ int s[512];
    int i = blockIdx.x * 512 + threadIdx.x;
    int v = (i < n) ? g_deg[i] : 0;
    s[threadIdx.x] = v;
    __syncthreads();
    for (int off = 1; off < 512; off <<= 1) {
        int t = (threadIdx.x >= off) ? s[threadIdx.x - off] : 0;
        __syncthreads();
        s[threadIdx.x] += t;
        __syncthreads();
    }
    if (i < n) g_rp[i] = s[threadIdx.x] - v;
    if (threadIdx.x == 511) g_bsum[blockIdx.x] = s[511];
}
// scan of block sums folded in: each block reduces bsum[j < bid]
__global__ void k_scan3b(int n, int e, int nb) {
    __shared__ int s[512];
    int tid = threadIdx.x, bid = blockIdx.x;
    s[tid] = (tid < nb && tid < bid) ? g_bsum[tid] : 0;
    __syncthreads();
    for (int off = 256; off >= 1; off >>= 1) {
        if (tid < off) s[tid] += s[tid + off];
        __syncthreads();
    }
    int offv = s[0];
    int i = bid * 512 + tid;
    if (i < n) {
        int r = g_rp[i] + offv;
        g_rp[i] = r;
        g_cur[i] = r;
    }
    if (i == 0) g_rp[n] = e;
}
__global__ void k_scatter(const int* __restrict__ src, const int* __restrict__ dst, int e) {
    int i = blockIdx.x * blockDim.x + threadIdx.x;
    if (i < e) {
        int d = dst[i];
        int p = atomicAdd(&g_cur[d], 1);
        g_col[p] = src[i];
    }
}

// ---------------- aggregation: m[v] = mean_in h[src] (fp16 planes -> fp16 planes) ----------------
__global__ __launch_bounds__(256)
void k_aggm(int n) {
    int w = (blockIdx.x * 256 + threadIdx.x) >> 5;
    int lane = threadIdx.x & 31;
    if (w >= n) return;
    int beg = g_rp[w], end = g_rp[w + 1];

    const int chunk = lane >> 4, kb = (lane & 15) << 3;
    const char* Ab = (const char*)g_A;

    float4 acc = make_float4(0.f, 0.f, 0.f, 0.f);
    for (int e = beg; e < end; e += 4) {
        int i1 = min(e + 1, end - 1);
        int i2 = min(e + 2, end - 1);
        int i3 = min(e + 3, end - 1);
        int u0 = g_col[e], u1 = g_col[i1], u2 = g_col[i2], u3 = g_col[i3];
#define ROWADDR(u) (Ab + ((size_t)((u >> 7) * 4 + chunk)) * 16384 + \
                    (((u & 127) >> 3) << 10) + swz((((u & 127) & 7) << 7) + kb))
        uint2 q0 = *(const uint2*)ROWADDR(u0);
        uint2 q1 = *(const uint2*)ROWADDR(u1);
        uint2 q2 = *(const uint2*)ROWADDR(u2);
        uint2 q3 = *(const uint2*)ROWADDR(u3);
#undef ROWADDR
#define ACC4(q) do { \
        float2 f0 = __half22float2(*(__half2*)&(q).x); \
        float2 f1 = __half22float2(*(__half2*)&(q).y); \
        acc.x += f0.x; acc.y += f0.y; acc.z += f1.x; acc.w += f1.y; } while (0)
        ACC4(q0);
        if (e + 1 < end) ACC4(q1);
        if (e + 2 < end) ACC4(q2);
        if (e + 3 < end) ACC4(q3);
#undef ACC4
    }
    float inv = 1.0f / (float)max(end - beg, 1);
    acc.x *= inv; acc.y *= inv; acc.z *= inv; acc.w *= inv;

    int tile = w >> 7, r = w & 127;
    char* base = (char*)g_A + ((size_t)tile * 4 + 2 + chunk) * 16384;
    int off = ((r >> 3) << 10) + swz(((r & 7) << 7) + kb);
    *(uint2*)(base + off) = pack_h4(acc);
}

// ---------------- fp16 mma GEMM: D[128 x 128] = A[128 x 64*NC] * B[128 x 64*NC]^T ----------------
__device__ __forceinline__ void prefetch_chunk(char* smembase, int c, const uint4* gAt,
                                               const uint4* __restrict__ Bw, int tid) {
    char* buf = smembase + (c & 1) * 32768;
    const uint4* sa = gAt + (size_t)c * 1024;
    unsigned da = smem_u32(buf);
#pragma unroll
    for (int i = 0; i < 4; i++) cp16(da + (tid + i * 256) * 16, sa + tid + i * 256);
    const uint4* sb = Bw + (size_t)c * 1024;
    unsigned db = smem_u32(buf + 16384);
#pragma unroll
    for (int i = 0; i < 4; i++) cp16(db + (tid + i * 256) * 16, sb + tid + i * 256);
    cp_commit();
}

template <int NC, bool FINAL>
__global__ __launch_bounds__(256, 2)
void k_gemm_mma(const uint4* __restrict__ Bw, const float* __restrict__ bias,
                float* __restrict__ out, int n) {
    extern __shared__ char smem[];
    const int tid = threadIdx.x, wid = tid >> 5, lane = tid & 31;
    const int mh = wid >> 2, nq = wid & 3;
    const size_t tile = blockIdx.x;
    const unsigned sbase = smem_u32(smem);

    const uint4* gAt = g_A + tile * 4 * 1024;

    float acc[4][4][4];
#pragma unroll
    for (int a = 0; a < 4; a++)
#pragma unroll
        for (int b = 0; b < 4; b++)
#pragma unroll
            for (int c = 0; c < 4; c++) acc[a][b][c] = 0.f;

    const int arow = mh * 64 + (lane & 15);
    const int brow = nq * 32 + ((lane >> 4) << 3) + (lane & 7);

    prefetch_chunk(smem, 0, gAt, Bw, tid);

#pragma unroll 1
    for (int c = 0; c < NC; c++) {
        if (c < NC - 1) { prefetch_chunk(smem, c + 1, gAt, Bw, tid); cp_wait1(); }
        else cp_wait0();
        __syncthreads();

        unsigned bufu = sbase + (unsigned)((c & 1) * 32768);
        unsigned Ap = bufu, Bp = bufu + 16384u;
#pragma unroll
        for (int ks = 0; ks < 4; ks++) {
            unsigned afr[4][4];
            {
                int seg = ks * 2 + (lane >> 4);
                int inner = swz(((arow & 7) << 7) + seg * 16);
#pragma unroll
                for (int mt = 0; mt < 4; mt++)
                    ldm_x4(afr[mt], Ap + (unsigned)((((arow >> 3) + 2 * mt) << 10) + inner));
            }
            unsigned bfr[2][4];
            {
                int seg = ks * 2 + ((lane >> 3) & 1);
                int inner = swz(((brow & 7) << 7) + seg * 16);
#pragma unroll
                for (int nb = 0; nb < 2; nb++)
                    ldm_x4(bfr[nb], Bp + (unsigned)((((brow >> 3) + 2 * nb) << 10) + inner));
            }
#pragma unroll
            for (int mt = 0; mt < 4; mt++)
#pragma unroll
                for (int nt = 0; nt < 4; nt++)
                    mma_f16(acc[mt][nt], afr[mt],
                            bfr[nt >> 1][(nt & 1) * 2], bfr[nt >> 1][(nt & 1) * 2 + 1]);
        }
        __syncthreads();
    }

    // -------- epilogue --------
    const size_t base = tile * 128;
    const int rr = lane >> 2, cc = (lane & 3) * 2;

    if (FINAL) {
        float* stage = (float*)smem;   // stride 84 floats, cols 0..79
#pragma unroll
        for (int mt = 0; mt < 4; mt++)
#pragma unroll
            for (int nt = 0; nt < 4; nt++) {
                int col = nq * 32 + nt * 8 + cc;
                if (col < 80) {
                    int r = mh * 64 + mt * 16 + rr;
                    stage[r * 84 + col] = acc[mt][nt][0];
                    stage[r * 84 + col + 1] = acc[mt][nt][1];
                    stage[(r + 8) * 84 + col] = acc[mt][nt][2];
                    stage[(r + 8) * 84 + col + 1] = acc[mt][nt][3];
                }
            }
        __syncthreads();
        for (int t = tid; t < 128 * 20; t += 256) {
            int nn = t / 20, c4 = t % 20;
            size_t gn = base + nn;
            if (gn < (size_t)n)
                *(float4*)(out + gn * 80 + c4 * 4) = *(float4*)(stage + nn * 84 + c4 * 4);
        }
    } else {
        __half* stg = (__half*)smem;   // stride 132 halves
#pragma unroll
        for (int mt = 0; mt < 4; mt++)
#pragma unroll
            for (int nt = 0; nt < 4; nt++) {
                int r = mh * 64 + mt * 16 + rr;
                int col = nq * 32 + nt * 8 + cc;
                float bv0 = __ldg(bias + col), bv1 = __ldg(bias + col + 1);
                float v0 = fmaxf(acc[mt][nt][0] + bv0, 0.f);
                float v1 = fmaxf(acc[mt][nt][1] + bv1, 0.f);
                float v2 = fmaxf(acc[mt][nt][2] + bv0, 0.f);
                float v3 = fmaxf(acc[mt][nt][3] + bv1, 0.f);
                *(__half2*)(stg + r * 132 + col) = __floats2half2_rn(v0, v1);
                *(__half2*)(stg + (r + 8) * 132 + col) = __floats2half2_rn(v2, v3);
            }
        __syncthreads();
        for (int t = tid; t < 4096; t += 256) {
            int nn = t >> 5, g = t & 31;
            size_t gn = base + nn;
            if (gn < (size_t)n) {
                uint2 q = *(uint2*)(stg + nn * 132 + g * 4);
                int k0 = g * 4;
                int chunk = k0 >> 6, kb = (k0 & 63) << 1;
                char* bA = (char*)g_A + (tile * 4 + chunk) * 16384;
                int off = ((nn >> 3) << 10) + swz(((nn & 7) << 7) + kb);
                *(uint2*)(bA + off) = q;
            }
        }
    }
}

// ---------------- final aggregation: out[v] = s[v] + mean_t + b ----------------
__global__ __launch_bounds__(256)
void k_aggf(const float* __restrict__ st, const float* __restrict__ b,
            float* __restrict__ out, int n) {
    int w = (blockIdx.x * 256 + threadIdx.x) >> 5;
    int lane = threadIdx.x & 31;
    if (w >= n) return;
    int beg = g_rp[w], end = g_rp[w + 1];

    float a0 = 0.f, a1 = 0.f;
    for (int e = beg; e < end; e += 2) {
        int i1 = min(e + 1, end - 1);
        int u0 = g_col[e], u1 = g_col[i1];
        const float* t0 = st + (size_t)u0 * 80 + 40;
        const float* t1 = st + (size_t)u1 * 80 + 40;
        a0 += t0[lane];
        if (lane < 8) a1 += t0[32 + lane];
        if (e + 1 < end) {
            a0 += t1[lane];
            if (lane < 8) a1 += t1[32 + lane];
        }
    }
    float inv = 1.0f / (float)max(end - beg, 1);
    const float* sp = st + (size_t)w * 80;
    out[(size_t)w * 40 + lane] = fmaf(a0, inv, sp[lane] + __ldg(b + lane));
    if (lane < 8) {
        int f = 32 + lane;
        out[(size_t)w * 40 + f] = fmaf(a1, inv, sp[f] + __ldg(b + f));
    }
}

// ---------------- launch ----------------
extern "C" void kernel_launch(void* const* d_in, const int* in_sizes, int n_in,
                              void* d_out, int out_size) {
    const float* x   = (const float*)d_in[0];
    const int*   src = (const int*)d_in[1];
    const int*   dst = (const int*)d_in[2];
    const float* ws1 = (const float*)d_in[3];
    const float* wn1 = (const float*)d_in[4];
    const float* b1  = (const float*)d_in[5];
    const float* ws2 = (const float*)d_in[6];
    const float* wn2 = (const float*)d_in[7];
    const float* b2  = (const float*)d_in[8];
    const float* ws3 = (const float*)d_in[9];
    const float* wn3 = (const float*)d_in[10];
    const float* b3  = (const float*)d_in[11];
    const float* ws4 = (const float*)d_in[12];
    const float* wn4 = (const float*)d_in[13];
    const float* b4  = (const float*)d_in[14];

    const int n = in_sizes[0] / 128;
    const int E = in_sizes[1];
    const int tiles = (n + 127) / 128;

    const int SMEM = 2 * 32768;
    cudaFuncSetAttribute(k_gemm_mma<4, false>, cudaFuncAttributeMaxDynamicSharedMemorySize, SMEM);
    cudaFuncSetAttribute(k_gemm_mma<2, true>,  cudaFuncAttributeMaxDynamicSharedMemorySize, SMEM);

    float* pst;
    uint4* pB;
    cudaGetSymbolAddress((void**)&pst, g_st);
    cudaGetSymbolAddress((void**)&pB, g_B);

    // preps (prep_x also zeroes deg)
    k_prep_x<<<(n * 32 + 255) / 256, 256>>>(x, n);
    k_prep_wall<<<dim3(16, 4), 256>>>(ws1, wn1, ws2, wn2, ws3, wn3, ws4, wn4);

    // CSR build (by dst)
    k_count<<<(E + 255) / 256, 256>>>(dst, E);
    int nb = (n + 511) / 512;
    k_scan1<<<nb, 512>>>(n);
    k_scan3b<<<nb, 512>>>(n, E, nb);
    k_scatter<<<(E + 255) / 256, 256>>>(src, dst, E);

    const int ga = (n + 7) / 8;

    // L1..L3: aggregate-then-GEMM (fused [Ws|Wn], relu)
    k_aggm<<<ga, 256>>>(n);
    k_gemm_mma<4, false><<<tiles, 256, SMEM>>>(pB + 0 * 4096, b1, nullptr, n);
    k_aggm<<<ga, 256>>>(n);
    k_gemm_mma<4, false><<<tiles, 256, SMEM>>>(pB + 1 * 4096, b2, nullptr, n);
    k_aggm<<<ga, 256>>>(n);
    k_gemm_mma<4, false><<<tiles, 256, SMEM>>>(pB + 2 * 4096, b3, nullptr, n);
    // L4: GEMM-then-gather (st = [Ws4;Wn4] h3, K=128), then final agg -> d_out
    k_gemm_mma<2, true><<<tiles, 256, SMEM>>>(pB + 3 * 4096, b4, pst, n);
    k_aggf<<<ga, 256>>>(pst, b4, (float*)d_out, n);
}